// round 4
// baseline (speedup 1.0000x reference)
#include <cuda_runtime.h>

// Problem dims (fixed)
#define Bv 4
#define Nv 256
#define Dv 128
#define Mv 128
#define Cv 128
#define ROWS (Bv * Nv)   // 1024

// Scratch (allocation-free: __device__ globals)
__device__ float g_pi[ROWS * Mv];     // 0.5*(h@W1a + b1)
__device__ float g_pj[ROWS * Mv];     // 0.5*(h@W1b)
__device__ float g_S [ROWS * Mv];     // masked adj-weighted silu sum
__device__ float g_amask[ROWS];       // sum_{j!=i} adj
__device__ float g_denom[ROWS];       // max(sum_j adj, 1)

// ---------------- packed f32x2 helpers ----------------
typedef unsigned long long ull;

__device__ __forceinline__ ull pk2(float v) {
    ull r; asm("mov.b64 %0, {%1,%1};" : "=l"(r) : "f"(v)); return r;
}
__device__ __forceinline__ void fma2(ull& d, ull a, ull b) {
    asm("fma.rn.f32x2 %0, %1, %2, %0;" : "+l"(d) : "l"(a), "l"(b));
}
__device__ __forceinline__ void upk2(ull v, float& lo, float& hi) {
    asm("mov.b64 {%0,%1}, %2;" : "=f"(lo), "=f"(hi) : "l"(v));
}
// silu(2*xh) where xh = x/2:  xh*(1+tanh(xh))
__device__ __forceinline__ float silu_h(float xh) {
    float t; asm("tanh.approx.f32 %0, %1;" : "=f"(t) : "f"(xh));
    return fmaf(xh, t, xh);
}

// ---------------------------------------------------------------------------
// K1: pre-GEMM. (1024x128)@(128x256), W=[W1a|W1b] fully staged in smem.
// 128 blocks x 256 threads, 8 rows/block. Thread: 2 rows x 4 cols, f32x2 FMA.
// Stores 0.5*(pi+b1) and 0.5*pj (pre-scaled for the tanh-silu in k_main).
// ---------------------------------------------------------------------------
__global__ __launch_bounds__(256) void k_pre(const float* __restrict__ h,
                                             const float* __restrict__ W1a,
                                             const float* __restrict__ W1b,
                                             const float* __restrict__ b1)
{
    extern __shared__ float dyn[];
    float* sW = dyn;               // [128][256]  = 128 KB
    float* sH = dyn + 128 * 256;   // [8][128]    = 4 KB

    const int row0 = blockIdx.x * 8;

    // Stage W (one pass, deep MLP)
    float4* s4 = (float4*)sW;
    for (int idx = threadIdx.x; idx < 8192; idx += 256) {
        int k = idx >> 6, c4 = idx & 63;
        s4[idx] = (c4 < 32) ? __ldg((const float4*)(W1a + k * Mv) + c4)
                            : __ldg((const float4*)(W1b + k * Mv) + (c4 - 32));
    }
    // Stage 8 rows of h
    {
        int r = threadIdx.x >> 5, c4 = threadIdx.x & 31;
        ((float4*)sH)[threadIdx.x] = __ldg((const float4*)(h + (row0 + r) * Dv) + c4);
    }
    __syncthreads();

    const int q = threadIdx.x >> 6;          // rows q and q+4
    const int c = (threadIdx.x & 63) * 4;    // 4 cols

    ull a00 = 0, a01 = 0, a10 = 0, a11 = 0;
    const float* H0 = sH + q * Dv;
    const float* H1 = sH + (q + 4) * Dv;

    #pragma unroll 8
    for (int k = 0; k < Dv; ++k) {
        ulonglong2 w = *(const ulonglong2*)(sW + k * 256 + c);
        ull h0 = pk2(H0[k]);
        ull h1 = pk2(H1[k]);
        fma2(a00, h0, w.x); fma2(a01, h0, w.y);
        fma2(a10, h1, w.x); fma2(a11, h1, w.y);
    }

    float v[2][4];
    upk2(a00, v[0][0], v[0][1]); upk2(a01, v[0][2], v[0][3]);
    upk2(a10, v[1][0], v[1][1]); upk2(a11, v[1][2], v[1][3]);

    #pragma unroll
    for (int rr = 0; rr < 2; ++rr) {
        const int row = row0 + q + rr * 4;
        if (c < 128) {
            #pragma unroll
            for (int t = 0; t < 4; ++t)
                g_pi[row * Mv + c + t] = 0.5f * (v[rr][t] + __ldg(b1 + c + t));
        } else {
            const int cm = c - 128;
            #pragma unroll
            for (int t = 0; t < 4; ++t)
                g_pj[row * Mv + cm + t] = 0.5f * v[rr][t];
        }
    }
}

// ---------------------------------------------------------------------------
// K2: pairwise silu-sum. 256 blocks x 128 threads. One warp per i-row:
// lane owns 4 m's (float4). One tanh per element; diagonal removed after loop.
// ---------------------------------------------------------------------------
__global__ __launch_bounds__(128) void k_main(const float* __restrict__ adj)
{
    const int b    = blockIdx.x >> 6;
    const int i    = ((blockIdx.x & 63) << 2) + (threadIdx.x >> 5);
    const int lane = threadIdx.x & 31;
    const int rowA = b * Nv + i;

    const float4* __restrict__ adj4 = (const float4*)(adj + (size_t)rowA * Nv);

    // adj row sums via warp shuffles (no smem, no block barriers)
    float4 s0 = __ldg(adj4 + lane);
    float4 s1 = __ldg(adj4 + lane + 32);
    float rs = (s0.x + s0.y) + (s0.z + s0.w) + (s1.x + s1.y) + (s1.z + s1.w);
    #pragma unroll
    for (int o = 16; o; o >>= 1) rs += __shfl_xor_sync(0xffffffffu, rs, o);
    const float aii = __ldg(adj + (size_t)rowA * Nv + i);
    if (lane == 0) {
        g_denom[rowA] = fmaxf(rs, 1.0f);
        g_amask[rowA] = rs - aii;
    }

    const int m4 = lane * 4;
    const float4 hpi = *(const float4*)(g_pi + rowA * Mv + m4);
    const float4* __restrict__ pj4 = (const float4*)(g_pj + (size_t)(b * Nv) * Mv) + lane;

    float4 acc = {0.f, 0.f, 0.f, 0.f};

    #pragma unroll 2
    for (int j = 0; j < Nv; j += 4) {
        float4 av = __ldg(adj4 + (j >> 2));
        #pragma unroll
        for (int t = 0; t < 4; ++t) {
            const float a = (t == 0) ? av.x : (t == 1) ? av.y : (t == 2) ? av.z : av.w;
            float4 p = __ldg(pj4 + (j + t) * 32);
            acc.x = fmaf(a, silu_h(hpi.x + p.x), acc.x);
            acc.y = fmaf(a, silu_h(hpi.y + p.y), acc.y);
            acc.z = fmaf(a, silu_h(hpi.z + p.z), acc.z);
            acc.w = fmaf(a, silu_h(hpi.w + p.w), acc.w);
        }
    }

    // remove diagonal j==i contribution
    {
        float4 p = __ldg(pj4 + i * 32);
        acc.x = fmaf(-aii, silu_h(hpi.x + p.x), acc.x);
        acc.y = fmaf(-aii, silu_h(hpi.y + p.y), acc.y);
        acc.z = fmaf(-aii, silu_h(hpi.z + p.z), acc.z);
        acc.w = fmaf(-aii, silu_h(hpi.w + p.w), acc.w);
    }

    *(float4*)(g_S + rowA * Mv + m4) = acc;
}

// ---------------------------------------------------------------------------
// K3: fused epilogue. 128 blocks x 256 threads, 8 rows/block.
// All three 128x128 weights staged once in 192 KB dynamic smem.
// Each row is owned by exactly one warp -> phases separated by __syncwarp().
// ---------------------------------------------------------------------------
__device__ __forceinline__ void gemm_row_f32x2(const float* __restrict__ Wsm,
                                               const float* __restrict__ in,
                                               int c, ull& a0, ull& a1)
{
    a0 = 0; a1 = 0;
    #pragma unroll 8
    for (int k = 0; k < Mv; ++k) {
        ulonglong2 w = *(const ulonglong2*)(Wsm + k * Mv + c);
        ull ap = pk2(in[k]);
        fma2(a0, ap, w.x);
        fma2(a1, ap, w.y);
    }
}

__global__ __launch_bounds__(256) void k_post(const float* __restrict__ W2,  const float* __restrict__ b2,
                                              const float* __restrict__ Wc1, const float* __restrict__ bc1,
                                              const float* __restrict__ Wc2, const float* __restrict__ bc2,
                                              float* __restrict__ out)
{
    extern __shared__ float sw[];                 // 3 x 128x128 = 192 KB
    __shared__ float bufA[8][Mv];
    __shared__ float bufB[8][Mv];

    const int row0 = blockIdx.x * 8;

    // Stage all three weights (one pass)
    {
        float4* s4 = (float4*)sw;
        for (int idx = threadIdx.x; idx < 3 * 4096; idx += 256) {
            const float* src = (idx < 4096) ? W2 : (idx < 8192 ? Wc1 : Wc2);
            s4[idx] = __ldg((const float4*)src + (idx & 4095));
        }
    }
    // Stage 8 rows of S
    for (int idx = threadIdx.x; idx < 8 * Mv / 4; idx += 256)
        ((float4*)bufA)[idx] = *((const float4*)(g_S + (size_t)row0 * Mv) + idx);
    __syncthreads();

    const int r   = threadIdx.x >> 5;        // row within block (one warp per row)
    const int c   = (threadIdx.x & 31) * 4;  // 4 output cols
    const int row = row0 + r;

    ull a0, a1;
    float o0, o1, o2, o3;

    // Phase A: m_agg = (S@W2 + b2*amask) / denom
    gemm_row_f32x2(sw, &bufA[r][0], c, a0, a1);
    upk2(a0, o0, o1); upk2(a1, o2, o3);
    {
        const float am  = g_amask[row];
        const float inv = __fdividef(1.0f, g_denom[row]);
        bufB[r][c + 0] = fmaf(__ldg(b2 + c + 0), am, o0) * inv;
        bufB[r][c + 1] = fmaf(__ldg(b2 + c + 1), am, o1) * inv;
        bufB[r][c + 2] = fmaf(__ldg(b2 + c + 2), am, o2) * inv;
        bufB[r][c + 3] = fmaf(__ldg(b2 + c + 3), am, o3) * inv;
    }
    __syncwarp();

    // Phase B: t = silu(m_agg@Wc1 + bc1)
    gemm_row_f32x2(sw + 128 * 128, &bufB[r][0], c, a0, a1);
    upk2(a0, o0, o1); upk2(a1, o2, o3);
    {
        float u0 = 0.5f * (o0 + __ldg(bc1 + c + 0));
        float u1 = 0.5f * (o1 + __ldg(bc1 + c + 1));
        float u2 = 0.5f * (o2 + __ldg(bc1 + c + 2));
        float u3 = 0.5f * (o3 + __ldg(bc1 + c + 3));
        bufA[r][c + 0] = silu_h(u0);
        bufA[r][c + 1] = silu_h(u1);
        bufA[r][c + 2] = silu_h(u2);
        bufA[r][c + 3] = silu_h(u3);
    }
    __syncwarp();

    // Phase C: out = t@Wc2 + bc2
    gemm_row_f32x2(sw + 2 * 128 * 128, &bufA[r][0], c, a0, a1);
    upk2(a0, o0, o1); upk2(a1, o2, o3);
    out[row * Cv + c + 0] = o0 + __ldg(bc2 + c + 0);
    out[row * Cv + c + 1] = o1 + __ldg(bc2 + c + 1);
    out[row * Cv + c + 2] = o2 + __ldg(bc2 + c + 2);
    out[row * Cv + c + 3] = o3 + __ldg(bc2 + c + 3);
}

// ---------------------------------------------------------------------------
// Launch. Inputs: 0:h 1:adj 2:W1a 3:W1b 4:b1 5:W2 6:b2 7:Wc1 8:bc1 9:Wc2 10:bc2
// ---------------------------------------------------------------------------
extern "C" void kernel_launch(void* const* d_in, const int* in_sizes, int n_in,
                              void* d_out, int out_size)
{
    (void)in_sizes; (void)n_in; (void)out_size;
    const float* h   = (const float*)d_in[0];
    const float* adj = (const float*)d_in[1];
    const float* W1a = (const float*)d_in[2];
    const float* W1b = (const float*)d_in[3];
    const float* b1  = (const float*)d_in[4];
    const float* W2  = (const float*)d_in[5];
    const float* b2  = (const float*)d_in[6];
    const float* Wc1 = (const float*)d_in[7];
    const float* bc1 = (const float*)d_in[8];
    const float* Wc2 = (const float*)d_in[9];
    const float* bc2 = (const float*)d_in[10];
    float* out = (float*)d_out;

    static bool attr_done = false;
    if (!attr_done) {
        cudaFuncSetAttribute(k_pre,  cudaFuncAttributeMaxDynamicSharedMemorySize, 135168);
        cudaFuncSetAttribute(k_post, cudaFuncAttributeMaxDynamicSharedMemorySize, 196608);
        attr_done = true;
    }

    k_pre <<<ROWS / 8, 256, 135168>>>(h, W1a, W1b, b1);
    k_main<<<ROWS / 4, 128>>>(adj);
    k_post<<<ROWS / 8, 256, 196608>>>(W2, b2, Wc1, bc1, Wc2, bc2, out);
}

// round 6
// speedup vs baseline: 1.6213x; 1.6213x over previous
#include <cuda_runtime.h>

// Problem dims (fixed)
#define Bv 4
#define Nv 256
#define Dv 128
#define Mv 128
#define Cv 128
#define ROWS 1024

#define NB 128          // persistent blocks (<= SM count, 1/SM resident)
#define NT 512          // threads per block (16 warps)

// Scratch (allocation-free: __device__ globals)
__device__ float g_pi[ROWS * Mv];     // 0.5*(h@W1a + b1)
__device__ float g_pj[ROWS * Mv];     // 0.5*(h@W1b)
__device__ float g_S [ROWS * Mv];     // masked adj-weighted silu sum
__device__ float g_amask[ROWS];       // sum_{j!=i} adj
__device__ float g_denom[ROWS];       // max(sum_j adj, 1)
__device__ unsigned g_count = 0;      // monotone grid-barrier counter (never reset)

typedef unsigned long long ull;

// ---------------- packed f32x2 helpers ----------------
__device__ __forceinline__ ull pk2(float v) {
    ull r; asm("mov.b64 %0, {%1,%1};" : "=l"(r) : "f"(v)); return r;
}
__device__ __forceinline__ void fma2(ull& d, ull a, ull b) {
    asm("fma.rn.f32x2 %0, %1, %2, %0;" : "+l"(d) : "l"(a), "l"(b));
}
__device__ __forceinline__ void upk2(ull v, float& lo, float& hi) {
    asm("mov.b64 {%0,%1}, %2;" : "=f"(lo), "=f"(hi) : "l"(v));
}
// silu(2*xh) where xh = x/2:  xh*(1+tanh(xh))
__device__ __forceinline__ float silu_h(float xh) {
    float t; asm("tanh.approx.f32 %0, %1;" : "=f"(t) : "f"(xh));
    return fmaf(xh, t, xh);
}

// ---------------- software grid barrier (monotone, reset-free) ----------------
__device__ __forceinline__ void grid_bar() {
    __syncthreads();
    if (threadIdx.x == 0) {
        __threadfence();
        unsigned my   = atomicAdd(&g_count, 1u);
        unsigned need = (my / NB + 1u) * NB;
        unsigned cur;
        for (;;) {
            asm volatile("ld.acquire.gpu.u32 %0, [%1];"
                         : "=r"(cur) : "l"(&g_count) : "memory");
            if (cur >= need) break;
            __nanosleep(64);
        }
    }
    __syncthreads();
}

// ---------------------------------------------------------------------------
// Fused persistent kernel: pre-GEMM -> barrier -> pairwise silu -> barrier ->
// triple GEMM epilogue. 128 blocks x 512 threads, 24 KB static smem.
// ---------------------------------------------------------------------------
__global__ __launch_bounds__(NT, 1)
void k_fused(const float* __restrict__ h,   const float* __restrict__ adj,
             const float* __restrict__ W1a, const float* __restrict__ W1b,
             const float* __restrict__ b1,
             const float* __restrict__ W2,  const float* __restrict__ b2,
             const float* __restrict__ Wc1, const float* __restrict__ bc1,
             const float* __restrict__ Wc2, const float* __restrict__ bc2,
             float* __restrict__ out)
{
    __shared__ ull sIn[8][Mv];      // duplicated f32x2 packs of current rows (8 KB)
    __shared__ ull sP[4][8][64];    // k-split partial accumulators (16 KB)

    const int bid  = blockIdx.x;
    const int tid  = threadIdx.x;
    const int wid  = tid >> 5;
    const int lane = tid & 31;

    // =====================================================================
    // Phase 1: pre-GEMM  (1024x128)@(128x256), W = [W1a | W1b].
    // 64 chunks x 16 rows. Warp covers 8 rows x 32 cols; lane = (row, colgrp)
    // so W loads are 4-way deduped within the warp (one 128B line per k).
    // =====================================================================
    if (bid < 64) {
        const int row = (bid << 4) + ((wid & 1) << 3) + (lane >> 2);
        const int cb  = ((wid >> 1) << 5) + ((lane & 3) << 3);   // 8 cols
        const bool isA = (cb < 128);
        const float* __restrict__ Wp = isA ? (W1a + cb) : (W1b + (cb - 128));
        const float* __restrict__ hp = h + row * Dv;

        ull a0 = 0, a1 = 0, a2 = 0, a3 = 0;
        #pragma unroll 4
        for (int k0 = 0; k0 < Dv; k0 += 4) {
            float4 hq = __ldg((const float4*)(hp + k0));
            #pragma unroll
            for (int t = 0; t < 4; ++t) {
                float hv = (t == 0) ? hq.x : (t == 1) ? hq.y : (t == 2) ? hq.z : hq.w;
                ull hh = pk2(hv);
                const float* wr = Wp + (k0 + t) * Mv;
                ulonglong2 wA = __ldg((const ulonglong2*)wr);
                ulonglong2 wB = __ldg((const ulonglong2*)(wr + 4));
                fma2(a0, hh, wA.x); fma2(a1, hh, wA.y);
                fma2(a2, hh, wB.x); fma2(a3, hh, wB.y);
            }
        }
        float v0,v1,v2,v3,v4,v5,v6,v7;
        upk2(a0,v0,v1); upk2(a1,v2,v3); upk2(a2,v4,v5); upk2(a3,v6,v7);

        if (isA) {
            float4 bA = __ldg((const float4*)(b1 + cb));
            float4 bB = __ldg((const float4*)(b1 + cb + 4));
            float4 o0 = make_float4(0.5f*(v0+bA.x), 0.5f*(v1+bA.y),
                                    0.5f*(v2+bA.z), 0.5f*(v3+bA.w));
            float4 o1 = make_float4(0.5f*(v4+bB.x), 0.5f*(v5+bB.y),
                                    0.5f*(v6+bB.z), 0.5f*(v7+bB.w));
            *(float4*)(g_pi + row * Mv + cb)     = o0;
            *(float4*)(g_pi + row * Mv + cb + 4) = o1;
        } else {
            const int cm = cb - 128;
            float4 o0 = make_float4(0.5f*v0, 0.5f*v1, 0.5f*v2, 0.5f*v3);
            float4 o1 = make_float4(0.5f*v4, 0.5f*v5, 0.5f*v6, 0.5f*v7);
            *(float4*)(g_pj + row * Mv + cm)     = o0;
            *(float4*)(g_pj + row * Mv + cm + 4) = o1;
        }
    }

    grid_bar();

    // =====================================================================
    // Phase 2: pairwise silu sum. 2048 units = (i, m-half): exactly one
    // unit per warp across 128 blocks x 16 warps. Lane owns 2 m's.
    // =====================================================================
    {
        const int u  = (bid << 4) + wid;       // 0..2047
        const int ig = u >> 1;                 // global row 0..1023
        const int b  = ig >> 8;
        const int i  = ig & 255;
        const int m0 = ((u & 1) << 6) + (lane << 1);
        const float* __restrict__ adjr = adj + (size_t)ig * Nv;

        const float aii = __ldg(adjr + i);

        if ((u & 1) == 0) {   // one warp per row does the adj reduction
            float4 s0 = __ldg((const float4*)adjr + lane);
            float4 s1 = __ldg((const float4*)adjr + 32 + lane);
            float rs = ((s0.x+s0.y)+(s0.z+s0.w)) + ((s1.x+s1.y)+(s1.z+s1.w));
            #pragma unroll
            for (int o = 16; o; o >>= 1) rs += __shfl_xor_sync(0xffffffffu, rs, o);
            if (lane == 0) {
                g_denom[ig] = fmaxf(rs, 1.0f);
                g_amask[ig] = rs - aii;
            }
        }

        float2 piv = __ldg((const float2*)(g_pi + ig * Mv + m0));
        const float pix = piv.x, piy = piv.y;
        const float* __restrict__ pjb = g_pj + ((size_t)b * Nv) * Mv + m0;

        float ax = 0.f, ay = 0.f;
        #pragma unroll 2
        for (int j = 0; j < Nv; j += 4) {
            float4 av = __ldg((const float4*)adjr + (j >> 2));
            #pragma unroll
            for (int t = 0; t < 4; ++t) {
                float a = (t == 0) ? av.x : (t == 1) ? av.y : (t == 2) ? av.z : av.w;
                float2 p = __ldg((const float2*)(pjb + (j + t) * Mv));
                ax = fmaf(a, silu_h(pix + p.x), ax);
                ay = fmaf(a, silu_h(piy + p.y), ay);
            }
        }
        // subtract diagonal j==i term
        {
            float2 p = __ldg((const float2*)(pjb + i * Mv));
            ax = fmaf(-aii, silu_h(pix + p.x), ax);
            ay = fmaf(-aii, silu_h(piy + p.y), ay);
        }
        *(float2*)(g_S + ig * Mv + m0) = make_float2(ax, ay);
    }

    grid_bar();

    // =====================================================================
    // Phase 3: chained GEMMs, chunk = 8 rows, 128 chunks (all blocks busy).
    // 4-way k-split: kseg = tid>>7; thread does 4 rows x 1 col-pair (f32x2).
    // Weights read as 64-bit words straight into f32x2 operands (no packing).
    // =====================================================================
    {
        const int row0 = bid << 3;
        const int kseg = tid >> 7;          // 0..3
        const int rowg = (tid >> 6) & 1;    // 0..1  -> rows {rowg, +2, +4, +6}
        const int cp   = tid & 63;          // col pair
        const int rrow = tid >> 6;          // reduce: output row 0..7
        const int rc   = (tid & 63) << 1;   // reduce: output col (even)

        // load S rows as duplicated packs
        for (int idx = tid; idx < 8 * Mv; idx += NT)
            sIn[idx >> 7][idx & 127] = pk2(__ldg(g_S + row0 * Mv + idx));
        __syncthreads();

        #pragma unroll 1
        for (int phase = 0; phase < 3; ++phase) {
            const float* W = (phase == 0) ? W2 : (phase == 1) ? Wc1 : Wc2;
            ull a0 = 0, a1 = 0, a2 = 0, a3 = 0;
            const ull* __restrict__ Wp = (const ull*)W + cp;
            #pragma unroll 8
            for (int kk = 0; kk < 32; ++kk) {
                const int k = (kseg << 5) + kk;
                ull wp = __ldg(Wp + (k << 6));
                fma2(a0, sIn[rowg    ][k], wp);
                fma2(a1, sIn[rowg + 2][k], wp);
                fma2(a2, sIn[rowg + 4][k], wp);
                fma2(a3, sIn[rowg + 6][k], wp);
            }
            sP[kseg][rowg    ][cp] = a0;
            sP[kseg][rowg + 2][cp] = a1;
            sP[kseg][rowg + 4][cp] = a2;
            sP[kseg][rowg + 6][cp] = a3;
            __syncthreads();

            // reduce 4 k-segments + epilogue for 2 outputs per thread
            float vx = 0.f, vy = 0.f;
            #pragma unroll
            for (int ks = 0; ks < 4; ++ks) {
                float px, py; upk2(sP[ks][rrow][tid & 63], px, py);
                vx += px; vy += py;
            }
            const int grow = row0 + rrow;
            if (phase == 0) {
                float am  = __ldg(g_amask + grow);
                float inv = __fdividef(1.0f, __ldg(g_denom + grow));
                float2 bb = __ldg((const float2*)(b2 + rc));
                sIn[rrow][rc]     = pk2(fmaf(bb.x, am, vx) * inv);
                sIn[rrow][rc + 1] = pk2(fmaf(bb.y, am, vy) * inv);
            } else if (phase == 1) {
                float2 bb = __ldg((const float2*)(bc1 + rc));
                sIn[rrow][rc]     = pk2(silu_h(0.5f * (vx + bb.x)));
                sIn[rrow][rc + 1] = pk2(silu_h(0.5f * (vy + bb.y)));
            } else {
                float2 bb = __ldg((const float2*)(bc2 + rc));
                *(float2*)(out + grow * Cv + rc) = make_float2(vx + bb.x, vy + bb.y);
            }
            __syncthreads();
        }
    }
}

// ---------------------------------------------------------------------------
// Launch. Inputs: 0:h 1:adj 2:W1a 3:W1b 4:b1 5:W2 6:b2 7:Wc1 8:bc1 9:Wc2 10:bc2
// ---------------------------------------------------------------------------
extern "C" void kernel_launch(void* const* d_in, const int* in_sizes, int n_in,
                              void* d_out, int out_size)
{
    (void)in_sizes; (void)n_in; (void)out_size;
    k_fused<<<NB, NT>>>((const float*)d_in[0], (const float*)d_in[1],
                        (const float*)d_in[2], (const float*)d_in[3],
                        (const float*)d_in[4], (const float*)d_in[5],
                        (const float*)d_in[6], (const float*)d_in[7],
                        (const float*)d_in[8], (const float*)d_in[9],
                        (const float*)d_in[10], (float*)d_out);
}

// round 8
// speedup vs baseline: 1.6331x; 1.0073x over previous
#include <cuda_runtime.h>

// Problem dims (fixed)
#define Bv 4
#define Nv 256
#define Dv 128
#define Mv 128
#define Cv 128
#define ROWS 1024

// Scratch (allocation-free: __device__ globals)
__device__ float g_pi[ROWS * Mv];       // 0.5*(h@W1a + b1)
__device__ float g_pj[ROWS * Mv];       // 0.5*(h@W1b)
__device__ float g_S0[ROWS * Mv];       // partial silu sum, j in [0,128)
__device__ float g_S1[ROWS * Mv];       // partial silu sum, j in [128,256)
__device__ float g_amask[ROWS];         // sum_{j!=i} adj
__device__ float g_denom[ROWS];         // max(sum_j adj, 1)

typedef unsigned long long ull;

// ---------------- packed f32x2 helpers ----------------
__device__ __forceinline__ ull pk2(float v) {
    ull r; asm("mov.b64 %0, {%1,%1};" : "=l"(r) : "f"(v)); return r;
}
__device__ __forceinline__ ull pkab(float a, float b) {
    ull r; asm("mov.b64 %0, {%1,%2};" : "=l"(r) : "f"(a), "f"(b)); return r;
}
__device__ __forceinline__ void fma2(ull& d, ull a, ull b) {
    asm("fma.rn.f32x2 %0, %1, %2, %0;" : "+l"(d) : "l"(a), "l"(b));
}
__device__ __forceinline__ ull add2(ull a, ull b) {
    ull r; asm("add.rn.f32x2 %0, %1, %2;" : "=l"(r) : "l"(a), "l"(b)); return r;
}
__device__ __forceinline__ void upk2(ull v, float& lo, float& hi) {
    asm("mov.b64 {%0,%1}, %2;" : "=f"(lo), "=f"(hi) : "l"(v));
}
__device__ __forceinline__ float tanh_ap(float x) {
    float t; asm("tanh.approx.f32 %0, %1;" : "=f"(t) : "f"(x)); return t;
}
// silu(2*xh) where xh = x/2:  xh*(1+tanh(xh))
__device__ __forceinline__ float silu_h(float xh) {
    return fmaf(xh, tanh_ap(xh), xh);
}
// packed silu_h on a f32x2 pair
__device__ __forceinline__ ull silu_h2(ull x2) {
    float x, y; upk2(x2, x, y);
    ull t2 = pkab(tanh_ap(x), tanh_ap(y));
    ull s2 = x2;
    fma2(s2, x2, t2);          // x2*t2 + x2
    return s2;
}

// ---------------------------------------------------------------------------
// K1: pre-GEMM. (1024x128)@(128x256), W=[W1a|W1b]. 256 blocks x 256 thr.
// Warp = 4 rows x 32 cols; lane = (row=lane>>3, colgrp=lane&7, 4 cols each).
// W loads are 8-way lane-deduped (one 128B line per k per warp).
// Stores 0.5*(pi+b1) and 0.5*pj (pre-scaled for tanh-silu).
// ---------------------------------------------------------------------------
__global__ __launch_bounds__(256) void k_pre(const float* __restrict__ h,
                                             const float* __restrict__ W1a,
                                             const float* __restrict__ W1b,
                                             const float* __restrict__ b1)
{
    const int wid  = threadIdx.x >> 5;
    const int lane = threadIdx.x & 31;
    const int row  = (blockIdx.x << 2) + (lane >> 3);
    const int c    = (wid << 5) + ((lane & 7) << 2);     // 4 cols
    const bool isA = (c < 128);
    const float* __restrict__ Wp = isA ? (W1a + c) : (W1b + (c - 128));
    const float* __restrict__ hp = h + row * Dv;

    ull a0 = 0, a1 = 0;
    #pragma unroll 4
    for (int k0 = 0; k0 < Dv; k0 += 4) {
        float4 hq = __ldg((const float4*)(hp + k0));
        #pragma unroll
        for (int t = 0; t < 4; ++t) {
            float hv = (t == 0) ? hq.x : (t == 1) ? hq.y : (t == 2) ? hq.z : hq.w;
            ull hh = pk2(hv);
            ulonglong2 w = __ldg((const ulonglong2*)(Wp + (k0 + t) * Mv));
            fma2(a0, hh, w.x);
            fma2(a1, hh, w.y);
        }
    }
    float v0, v1, v2, v3;
    upk2(a0, v0, v1); upk2(a1, v2, v3);

    if (isA) {
        float4 bb = __ldg((const float4*)(b1 + c));
        *(float4*)(g_pi + row * Mv + c) =
            make_float4(0.5f*(v0+bb.x), 0.5f*(v1+bb.y), 0.5f*(v2+bb.z), 0.5f*(v3+bb.w));
    } else {
        *(float4*)(g_pj + row * Mv + (c - 128)) =
            make_float4(0.5f*v0, 0.5f*v1, 0.5f*v2, 0.5f*v3);
    }
}

// ---------------------------------------------------------------------------
// K2: pairwise silu sum, j-split 2. 512 blocks x 256 thr = 4096 warps.
// u = bid*8+wid -> (ig = u>>2, m-half = (u>>1)&1, j-half = u&1).
// Lane owns 2 m's; 128 j per warp; packed f32x2 math, 2 tanh per j.
// ---------------------------------------------------------------------------
__global__ __launch_bounds__(256) void k_main(const float* __restrict__ adj)
{
    const int wid  = threadIdx.x >> 5;
    const int lane = threadIdx.x & 31;
    const int u    = (blockIdx.x << 3) + wid;        // 0..4095
    const int ig   = u >> 2;                         // 0..1023
    const int b    = ig >> 8;
    const int i    = ig & 255;
    const int mh   = (u >> 1) & 1;
    const int jh   = u & 1;
    const int m0   = (mh << 6) + (lane << 1);
    const float* __restrict__ adjr = adj + (size_t)ig * Nv;

    const float aii = __ldg(adjr + i);

    if ((u & 3) == 0) {      // one warp per row: adj reduction
        float4 s0 = __ldg((const float4*)adjr + lane);
        float4 s1 = __ldg((const float4*)adjr + 32 + lane);
        float rs = ((s0.x+s0.y)+(s0.z+s0.w)) + ((s1.x+s1.y)+(s1.z+s1.w));
        #pragma unroll
        for (int o = 16; o; o >>= 1) rs += __shfl_xor_sync(0xffffffffu, rs, o);
        if (lane == 0) {
            g_denom[ig] = fmaxf(rs, 1.0f);
            g_amask[ig] = rs - aii;
        }
    }

    const ull pi2 = *(const ull*)(g_pi + ig * Mv + m0);
    const float* __restrict__ pjb = g_pj + ((size_t)b * Nv) * Mv + m0;

    ull acc2 = 0;
    const int j0 = jh << 7;
    #pragma unroll 4
    for (int j = j0; j < j0 + 128; j += 4) {
        float4 av = __ldg((const float4*)adjr + (j >> 2));   // uniform across warp
        #pragma unroll
        for (int t = 0; t < 4; ++t) {
            float a = (t == 0) ? av.x : (t == 1) ? av.y : (t == 2) ? av.z : av.w;
            ull p2 = __ldg((const ull*)(pjb + (j + t) * Mv));
            ull s2 = silu_h2(add2(pi2, p2));
            fma2(acc2, pk2(a), s2);
        }
    }

    // subtract diagonal if i falls in this warp's j-range
    if ((i >> 7) == jh) {
        ull p2 = __ldg((const ull*)(pjb + i * Mv));
        ull s2 = silu_h2(add2(pi2, p2));
        fma2(acc2, pk2(-aii), s2);
    }

    float* dst = (jh == 0) ? g_S0 : g_S1;
    *(ull*)(dst + ig * Mv + m0) = acc2;
}

// ---------------------------------------------------------------------------
// K3: chained GEMM epilogue. 128 blocks x 512 thr, 8 rows/block.
// 4-way k-split; thread does 4 rows x 1 col-pair (f32x2 straight from gmem).
// ---------------------------------------------------------------------------
__global__ __launch_bounds__(512) void k_post(const float* __restrict__ W2,  const float* __restrict__ b2,
                                              const float* __restrict__ Wc1, const float* __restrict__ bc1,
                                              const float* __restrict__ Wc2, const float* __restrict__ bc2,
                                              float* __restrict__ out)
{
    __shared__ ull sIn[8][Mv];      // duplicated f32x2 packs of current rows
    __shared__ ull sP[4][8][64];    // k-split partial accumulators

    const int tid  = threadIdx.x;
    const int row0 = blockIdx.x << 3;
    const int kseg = tid >> 7;          // 0..3
    const int rowg = (tid >> 6) & 1;    // rows {rowg, +2, +4, +6}
    const int cp   = tid & 63;          // col pair
    const int rrow = tid >> 6;          // reduce: output row 0..7
    const int rc   = (tid & 63) << 1;   // reduce: output col (even)

    for (int idx = tid; idx < 8 * Mv; idx += 512)
        sIn[idx >> 7][idx & 127] =
            pk2(__ldg(g_S0 + row0 * Mv + idx) + __ldg(g_S1 + row0 * Mv + idx));
    __syncthreads();

    #pragma unroll 1
    for (int phase = 0; phase < 3; ++phase) {
        const float* W = (phase == 0) ? W2 : (phase == 1) ? Wc1 : Wc2;
        ull a0 = 0, a1 = 0, a2 = 0, a3 = 0;
        const ull* __restrict__ Wp = (const ull*)W + cp;
        #pragma unroll 8
        for (int kk = 0; kk < 32; ++kk) {
            const int k = (kseg << 5) + kk;
            ull wp = __ldg(Wp + (k << 6));
            fma2(a0, sIn[rowg    ][k], wp);
            fma2(a1, sIn[rowg + 2][k], wp);
            fma2(a2, sIn[rowg + 4][k], wp);
            fma2(a3, sIn[rowg + 6][k], wp);
        }
        sP[kseg][rowg    ][cp] = a0;
        sP[kseg][rowg + 2][cp] = a1;
        sP[kseg][rowg + 4][cp] = a2;
        sP[kseg][rowg + 6][cp] = a3;
        __syncthreads();

        float vx = 0.f, vy = 0.f;
        #pragma unroll
        for (int ks = 0; ks < 4; ++ks) {
            float px, py; upk2(sP[ks][rrow][tid & 63], px, py);
            vx += px; vy += py;
        }
        const int grow = row0 + rrow;
        if (phase == 0) {
            float am  = __ldg(g_amask + grow);
            float inv = __fdividef(1.0f, __ldg(g_denom + grow));
            float2 bb = __ldg((const float2*)(b2 + rc));
            sIn[rrow][rc]     = pk2(fmaf(bb.x, am, vx) * inv);
            sIn[rrow][rc + 1] = pk2(fmaf(bb.y, am, vy) * inv);
        } else if (phase == 1) {
            float2 bb = __ldg((const float2*)(bc1 + rc));
            sIn[rrow][rc]     = pk2(silu_h(0.5f * (vx + bb.x)));
            sIn[rrow][rc + 1] = pk2(silu_h(0.5f * (vy + bb.y)));
        } else {
            float2 bb = __ldg((const float2*)(bc2 + rc));
            *(float2*)(out + grow * Cv + rc) = make_float2(vx + bb.x, vy + bb.y);
        }
        __syncthreads();
    }
}

// ---------------------------------------------------------------------------
// Launch. Inputs: 0:h 1:adj 2:W1a 3:W1b 4:b1 5:W2 6:b2 7:Wc1 8:bc1 9:Wc2 10:bc2
// ---------------------------------------------------------------------------
extern "C" void kernel_launch(void* const* d_in, const int* in_sizes, int n_in,
                              void* d_out, int out_size)
{
    (void)in_sizes; (void)n_in; (void)out_size;
    const float* h   = (const float*)d_in[0];
    const float* adj = (const float*)d_in[1];

    k_pre <<<256, 256>>>(h, (const float*)d_in[2], (const float*)d_in[3],
                         (const float*)d_in[4]);
    k_main<<<512, 256>>>(adj);
    k_post<<<128, 512>>>((const float*)d_in[5], (const float*)d_in[6],
                         (const float*)d_in[7], (const float*)d_in[8],
                         (const float*)d_in[9], (const float*)d_in[10],
                         (float*)d_out);
}